// round 6
// baseline (speedup 1.0000x reference)
#include <cuda_runtime.h>

// Inverted index scratch. g_head[row] -> first eid (-1 if none).
// g_next[eid] -> next eid (-1 terminator). eid = b*Kp1 + k == output offset.
#define MAX_N (1 << 20)        // >= 1,000,000 rows
#define MAX_E (1 << 21)        // >= 1,048,832 entries
__device__ int g_head[MAX_N];
__device__ int g_next[MAX_E];

// ----------------------------------------------------------------------------
// Kernel A: reset heads to -1, vectorized int4.
// ----------------------------------------------------------------------------
__global__ void init_head_kernel(int n4) {
    int i = blockIdx.x * blockDim.x + threadIdx.x;
    int stride = gridDim.x * blockDim.x;
    int4 mone = make_int4(-1, -1, -1, -1);
    int4* p = (int4*)g_head;
    for (; i < n4; i += stride) p[i] = mone;
}

// ----------------------------------------------------------------------------
// Kernel B: bin score entries into per-row chains.
// ----------------------------------------------------------------------------
__global__ void bin_kernel(const int* __restrict__ idx, int Kp1) {
    int k = blockIdx.x * blockDim.x + threadIdx.x;
    int b = blockIdx.y;
    if (k >= Kp1) return;
    int eid = b * Kp1 + k;
    int row = idx[eid];
    g_next[eid] = atomicExch(&g_head[row], eid);
}

// ----------------------------------------------------------------------------
// Kernel C: fused copy + scores + positive momentum update.
// Software-pipelined grid-stride: each warp prefetches the NEXT group's
// 4 rows (DRAM) and heads before doing the current group's stores + chain
// work, so pointer-chase/reduction latency hides under in-flight loads.
// Chain walk is wave-batched across the 4 rows (ILP on g_next / x loads).
// ----------------------------------------------------------------------------
#define RPW 4

template <int KP1C>
__global__ void __launch_bounds__(256)
fused_copy_score_kernel(const float4* __restrict__ mem4,
                        float4* __restrict__ dst4,
                        const float4* __restrict__ x4,
                        float* __restrict__ out,
                        int N, int Kp1_rt, float invT) {
    const int Kp1 = (KP1C > 0) ? KP1C : Kp1_rt;
    int lane = threadIdx.x & 31;
    int gw = (blockIdx.x * blockDim.x + threadIdx.x) >> 5;
    int nw = (gridDim.x * blockDim.x) >> 5;
    long long stride = (long long)nw * RPW;

    long long cur = (long long)gw * RPW;
    if (cur >= N) return;

    // Prologue: load first group
    float4 vc[RPW];
    int hdc[RPW];
    #pragma unroll
    for (int j = 0; j < RPW; j++) {
        long long r = cur + j;
        if (r < N) vc[j] = mem4[r * 32 + lane];
    }
    #pragma unroll
    for (int j = 0; j < RPW; j++) {
        long long r = cur + j;
        hdc[j] = (r < N) ? g_head[r] : -1;
    }

    while (true) {
        long long nxt = cur + stride;
        bool havenext = (nxt < N);

        // ---- Prefetch NEXT group (issues DRAM loads before any stalls) ----
        float4 vn[RPW];
        int hdn[RPW];
        if (havenext) {
            #pragma unroll
            for (int j = 0; j < RPW; j++) {
                long long r = nxt + j;
                if (r < N) vn[j] = mem4[r * 32 + lane];
            }
            #pragma unroll
            for (int j = 0; j < RPW; j++) {
                long long r = nxt + j;
                hdn[j] = (r < N) ? g_head[r] : -1;
            }
        }

        // ---- Copy stores for current group ----
        #pragma unroll
        for (int j = 0; j < RPW; j++) {
            long long r = cur + j;
            if (r < N) dst4[r * 32 + lane] = vc[j];
        }

        // ---- Chain work (overlaps with prefetched loads in flight) ----
        int all = -1;
        #pragma unroll
        for (int j = 0; j < RPW; j++) all &= hdc[j];
        if (all != -1) {
            int posb[RPW], e[RPW];
            #pragma unroll
            for (int j = 0; j < RPW; j++) { posb[j] = -1; e[j] = hdc[j]; }

            bool any = true;
            while (any) {
                // wave: batch all active rows' current entries
                int nx[RPW];
                float4 xv[RPW];
                unsigned int bb[RPW];
                float s[RPW];
                #pragma unroll
                for (int j = 0; j < RPW; j++)
                    nx[j] = (e[j] >= 0) ? g_next[e[j]] : -1;
                #pragma unroll
                for (int j = 0; j < RPW; j++) {
                    if (e[j] >= 0) {
                        bb[j] = (unsigned int)e[j] / (unsigned int)Kp1;
                        xv[j] = x4[bb[j] * 32 + lane];   // L1/L2-resident
                    }
                }
                #pragma unroll
                for (int j = 0; j < RPW; j++) {
                    s[j] = (e[j] >= 0)
                         ? vc[j].x * xv[j].x + vc[j].y * xv[j].y
                         + vc[j].z * xv[j].z + vc[j].w * xv[j].w
                         : 0.0f;
                }
                #pragma unroll
                for (int o = 16; o > 0; o >>= 1) {
                    #pragma unroll
                    for (int j = 0; j < RPW; j++)
                        s[j] += __shfl_xor_sync(0xffffffffu, s[j], o);
                }
                #pragma unroll
                for (int j = 0; j < RPW; j++) {
                    if (e[j] >= 0) {
                        int k = e[j] - (int)bb[j] * Kp1;
                        if (lane == 0) out[e[j]] = s[j] * invT;
                        if (k == 0) posb[j] = max(posb[j], (int)bb[j]);
                        e[j] = nx[j];
                    }
                }
                int a = -1;
                #pragma unroll
                for (int j = 0; j < RPW; j++) a &= e[j];
                any = (a != -1);
            }

            // ---- Momentum update overwrite (~256 rows grid-wide) ----
            #pragma unroll
            for (int j = 0; j < RPW; j++) {
                if (posb[j] >= 0) {
                    long long r = cur + j;
                    float4 xv = x4[posb[j] * 32 + lane];
                    float4 w;
                    w.x = 0.5f * vc[j].x + 0.5f * xv.x;
                    w.y = 0.5f * vc[j].y + 0.5f * xv.y;
                    w.z = 0.5f * vc[j].z + 0.5f * xv.z;
                    w.w = 0.5f * vc[j].w + 0.5f * xv.w;
                    float ss = w.x * w.x + w.y * w.y + w.z * w.z + w.w * w.w;
                    #pragma unroll
                    for (int o = 16; o > 0; o >>= 1)
                        ss += __shfl_xor_sync(0xffffffffu, ss, o);
                    float inv = 1.0f / sqrtf(ss);
                    w.x *= inv; w.y *= inv; w.z *= inv; w.w *= inv;
                    dst4[r * 32 + lane] = w;
                }
            }
        }

        if (!havenext) break;
        #pragma unroll
        for (int j = 0; j < RPW; j++) { vc[j] = vn[j]; hdc[j] = hdn[j]; }
        cur = nxt;
    }
}

// ----------------------------------------------------------------------------
// Launch. Inputs: x [B,D] f32, memory [N,D] f32, y [B] i32, idx [B,K+1] i32.
// Output: out [B,K+1] f32 then new_memory [N,D] f32.
// ----------------------------------------------------------------------------
extern "C" void kernel_launch(void* const* d_in, const int* in_sizes, int n_in,
                              void* d_out, int out_size) {
    const float* x      = (const float*)d_in[0];
    const float* memory = (const float*)d_in[1];
    const int*   idx    = (const int*)d_in[3];

    int B   = in_sizes[2];                  // 256
    int D   = in_sizes[0] / B;              // 128
    int Kp1 = in_sizes[3] / B;              // 4097
    int N   = in_sizes[1] / D;              // 1,000,000

    float* out_scores = (float*)d_out;
    float* new_memory = (float*)d_out + (long long)in_sizes[3];

    const float invT = 1.0f / 0.07f;

    // A) reset chain heads
    {
        int n4 = (N + 3) / 4;
        int threads = 256;
        int blocks = (n4 + threads - 1) / threads;
        if (blocks > 4096) blocks = 4096;
        init_head_kernel<<<blocks, threads>>>(n4);
    }

    // B) bin score entries by memory row
    {
        dim3 grid((Kp1 + 255) / 256, B);
        bin_kernel<<<grid, 256>>>(idx, Kp1);
    }

    // C) fused copy + scores + positive update, software-pipelined grid-stride
    {
        int threads = 256;                      // 8 warps/block
        int rows_per_block = (threads / 32) * RPW;   // 32
        int max_blocks = 3848;                  // 148 SMs * 26 -> ~8 iters/warp
        int blocks = (N + rows_per_block - 1) / rows_per_block;
        if (blocks > max_blocks) blocks = max_blocks;
        if (Kp1 == 4097) {
            fused_copy_score_kernel<4097><<<blocks, threads>>>(
                (const float4*)memory, (float4*)new_memory,
                (const float4*)x, out_scores, N, Kp1, invT);
        } else {
            fused_copy_score_kernel<0><<<blocks, threads>>>(
                (const float4*)memory, (float4*)new_memory,
                (const float4*)x, out_scores, N, Kp1, invT);
        }
    }
}

// round 7
// speedup vs baseline: 1.1440x; 1.1440x over previous
#include <cuda_runtime.h>

// Inverted index scratch. g_head[row]: 0 = empty, else eid+1.
// g_next[eid]: 0 = end, else next_eid+1.  eid = b*Kp1 + k == output offset.
// Zero-initialized at module load; the fused kernel resets its rows' heads
// in its epilogue, so every launch (and every graph replay) starts clean.
#define MAX_N (1 << 20)        // >= 1,000,000 rows
#define MAX_E (1 << 21)        // >= 1,048,832 entries
__device__ int g_head[MAX_N];
__device__ int g_next[MAX_E];

// ----------------------------------------------------------------------------
// Kernel B: bin score entries into per-row chains (eid+1 encoding).
// ----------------------------------------------------------------------------
__global__ void bin_kernel(const int* __restrict__ idx, int Kp1) {
    int k = blockIdx.x * blockDim.x + threadIdx.x;
    int b = blockIdx.y;
    if (k >= Kp1) return;
    int eid = b * Kp1 + k;
    int row = idx[eid];
    g_next[eid] = atomicExch(&g_head[row], eid + 1);
}

// ----------------------------------------------------------------------------
// Kernel C: fused copy + scores + positive momentum update.
// One-shot grid, one warp per RPW=8 consecutive rows, EXACT coverage
// (N % (warps*RPW) == 0 -> no bounds checks, immediate-offset addressing).
// Copy is a pure batched load/store stream. Chain work is wave-batched
// across the 8 rows. Epilogue resets this warp's head entries to 0.
// ----------------------------------------------------------------------------
#define RPW 8

template <int KP1C, bool EXACT>
__global__ void __launch_bounds__(256)
fused_copy_score_kernel(const float4* __restrict__ mem4,
                        float4* __restrict__ dst4,
                        const float4* __restrict__ x4,
                        float* __restrict__ out,
                        int N, int Kp1_rt, float invT) {
    const int Kp1 = (KP1C > 0) ? KP1C : Kp1_rt;
    const int lane = threadIdx.x & 31;
    const int wg = (blockIdx.x * blockDim.x + threadIdx.x) >> 5;
    const int r0 = wg * RPW;
    if (!EXACT && r0 >= N) return;

    const float4* __restrict__ src = mem4 + (size_t)r0 * 32 + lane;
    float4*       __restrict__ dst = dst4 + (size_t)r0 * 32 + lane;

    // ---- Pure copy stream: batched loads, head loads, batched stores ----
    float4 v[RPW];
    int hd[RPW];
    #pragma unroll
    for (int j = 0; j < RPW; j++) {
        if (EXACT || r0 + j < N) v[j] = src[j * 32];   // LDG [R+512*j]
    }
    #pragma unroll
    for (int j = 0; j < RPW; j++) {
        hd[j] = (EXACT || r0 + j < N) ? g_head[r0 + j] : 0;
    }
    #pragma unroll
    for (int j = 0; j < RPW; j++) {
        if (EXACT || r0 + j < N) dst[j * 32] = v[j];   // STG [R+512*j]
    }

    // ---- Early out: no score entries anywhere in this group ----
    int any = 0;
    #pragma unroll
    for (int j = 0; j < RPW; j++) any |= hd[j];
    if (any == 0) return;                // heads already 0, no reset needed

    int posb[RPW], e[RPW];
    #pragma unroll
    for (int j = 0; j < RPW; j++) { posb[j] = -1; e[j] = hd[j]; }

    // ---- Wave-batched chain walk (wave count = max chain length, ~1-2) ----
    bool anyact = true;
    while (anyact) {
        int nx[RPW];
        unsigned int bb[RPW];
        float s[RPW];
        #pragma unroll
        for (int j = 0; j < RPW; j++)
            nx[j] = (e[j] > 0) ? g_next[e[j] - 1] : 0;
        #pragma unroll
        for (int j = 0; j < RPW; j++) {
            if (e[j] > 0) {
                bb[j] = (unsigned int)(e[j] - 1) / (unsigned int)Kp1;
                float4 xv = x4[bb[j] * 32 + lane];       // L1/L2-resident
                s[j] = v[j].x * xv.x + v[j].y * xv.y
                     + v[j].z * xv.z + v[j].w * xv.w;
            } else {
                s[j] = 0.0f;
            }
        }
        #pragma unroll
        for (int o = 16; o > 0; o >>= 1) {
            #pragma unroll
            for (int j = 0; j < RPW; j++)
                s[j] += __shfl_xor_sync(0xffffffffu, s[j], o);
        }
        #pragma unroll
        for (int j = 0; j < RPW; j++) {
            if (e[j] > 0) {
                int eid = e[j] - 1;
                int k = eid - (int)bb[j] * Kp1;
                if (lane == 0) out[eid] = s[j] * invT;
                if (k == 0) posb[j] = max(posb[j], (int)bb[j]);
                e[j] = nx[j];
            }
        }
        int a = 0;
        #pragma unroll
        for (int j = 0; j < RPW; j++) a |= e[j];
        anyact = (a != 0);
    }

    // ---- Momentum update overwrite (~256 rows grid-wide) ----
    #pragma unroll
    for (int j = 0; j < RPW; j++) {
        if (posb[j] >= 0) {
            float4 xv = x4[posb[j] * 32 + lane];
            float4 w;
            w.x = 0.5f * v[j].x + 0.5f * xv.x;
            w.y = 0.5f * v[j].y + 0.5f * xv.y;
            w.z = 0.5f * v[j].z + 0.5f * xv.z;
            w.w = 0.5f * v[j].w + 0.5f * xv.w;
            float ss = w.x * w.x + w.y * w.y + w.z * w.z + w.w * w.w;
            #pragma unroll
            for (int o = 16; o > 0; o >>= 1)
                ss += __shfl_xor_sync(0xffffffffu, ss, o);
            float inv = 1.0f / sqrtf(ss);
            w.x *= inv; w.y *= inv; w.z *= inv; w.w *= inv;
            dst[j * 32] = w;
        }
    }

    // ---- Reset this warp's heads for the next launch/replay ----
    if (lane < RPW) {
        if (EXACT || r0 + lane < N) g_head[r0 + lane] = 0;
    }
}

// ----------------------------------------------------------------------------
// Launch. Inputs: x [B,D] f32, memory [N,D] f32, y [B] i32, idx [B,K+1] i32.
// Output: out [B,K+1] f32 then new_memory [N,D] f32.
// ----------------------------------------------------------------------------
extern "C" void kernel_launch(void* const* d_in, const int* in_sizes, int n_in,
                              void* d_out, int out_size) {
    const float* x      = (const float*)d_in[0];
    const float* memory = (const float*)d_in[1];
    const int*   idx    = (const int*)d_in[3];

    int B   = in_sizes[2];                  // 256
    int D   = in_sizes[0] / B;              // 128
    int Kp1 = in_sizes[3] / B;              // 4097
    int N   = in_sizes[1] / D;              // 1,000,000

    float* out_scores = (float*)d_out;
    float* new_memory = (float*)d_out + (long long)in_sizes[3];

    const float invT = 1.0f / 0.07f;

    // B) bin score entries by memory row (heads are clean: zero-init on first
    //    launch, reset by the previous fused-kernel epilogue afterwards)
    {
        dim3 grid((Kp1 + 255) / 256, B);
        bin_kernel<<<grid, 256>>>(idx, Kp1);
    }

    // C) fused copy + scores + positive update
    {
        int threads = 256;                           // 8 warps/block
        int rows_per_block = (threads / 32) * RPW;   // 64
        int blocks = (N + rows_per_block - 1) / rows_per_block;
        bool exact = (N % rows_per_block) == 0;      // 1e6 / 64 = 15625 exact
        if (Kp1 == 4097 && exact) {
            fused_copy_score_kernel<4097, true><<<blocks, threads>>>(
                (const float4*)memory, (float4*)new_memory,
                (const float4*)x, out_scores, N, Kp1, invT);
        } else if (exact) {
            fused_copy_score_kernel<0, true><<<blocks, threads>>>(
                (const float4*)memory, (float4*)new_memory,
                (const float4*)x, out_scores, N, Kp1, invT);
        } else {
            fused_copy_score_kernel<0, false><<<blocks, threads>>>(
                (const float4*)memory, (float4*)new_memory,
                (const float4*)x, out_scores, N, Kp1, invT);
        }
    }
}

// round 8
// speedup vs baseline: 2.0087x; 1.7559x over previous
#include <cuda_runtime.h>

// Inverted index scratch. g_head[row]: 0 = empty, else eid+1.
// g_next[eid]: 0 = end, else next_eid+1.  eid = b*Kp1 + k == output offset.
// g_head is zero at module load; the fused kernel's epilogue resets every
// head it consumed back to 0, so each launch (and graph replay) starts clean.
#define MAX_N (1 << 20)        // >= 1,000,000 rows
#define MAX_E (1 << 21)        // >= 1,048,832 entries
__device__ int g_head[MAX_N];
__device__ int g_next[MAX_E];

// ----------------------------------------------------------------------------
// Kernel B: bin score entries into per-row chains (eid+1 encoding).
// ----------------------------------------------------------------------------
__global__ void bin_kernel(const int* __restrict__ idx, int Kp1) {
    int k = blockIdx.x * blockDim.x + threadIdx.x;
    int b = blockIdx.y;
    if (k >= Kp1) return;
    int eid = b * Kp1 + k;
    int row = idx[eid];
    g_next[eid] = atomicExch(&g_head[row], eid + 1);
}

// ----------------------------------------------------------------------------
// Kernel C: fused copy + scores + positive momentum update.
// R5-proven structure: one-shot grid, one warp per 8 consecutive rows.
//  - pure batched copy stream (8 loads, 8 head loads, 8 stores)
//  - first entries of all rows batched OUTSIDE any loop (one interleaved
//    8-wide shfl reduction)
//  - chains of length >= 2 handled by rare serial tail loops
//  - ~256 momentum rows get an overwriting second store
//  - epilogue resets this warp's heads to 0
// EXACT=true: N divisible by rows/block -> no bounds checks, immediate offsets.
// ----------------------------------------------------------------------------
#define RPW 8

template <int KP1C, bool EXACT>
__global__ void fused_copy_score_kernel(const float4* __restrict__ mem4,
                                        float4* __restrict__ dst4,
                                        const float4* __restrict__ x4,
                                        float* __restrict__ out,
                                        int N, int Kp1_rt, float invT) {
    const int Kp1 = (KP1C > 0) ? KP1C : Kp1_rt;
    const int lane = threadIdx.x & 31;
    const int wg = (blockIdx.x * blockDim.x + threadIdx.x) >> 5;
    const int r0 = wg * RPW;
    if (!EXACT && r0 >= N) return;

    const float4* __restrict__ src = mem4 + (size_t)r0 * 32 + lane;
    float4*       __restrict__ dst = dst4 + (size_t)r0 * 32 + lane;

    // ---- Pure copy stream: batched loads, head loads, batched stores ----
    float4 v[RPW];
    int hd[RPW];
    #pragma unroll
    for (int j = 0; j < RPW; j++) {
        if (EXACT || r0 + j < N) v[j] = src[j * 32];     // LDG.128 [R+512*j]
    }
    #pragma unroll
    for (int j = 0; j < RPW; j++) {
        hd[j] = (EXACT || r0 + j < N) ? g_head[r0 + j] : 0;
    }
    #pragma unroll
    for (int j = 0; j < RPW; j++) {
        if (EXACT || r0 + j < N) dst[j * 32] = v[j];     // STG.128 [R+512*j]
    }

    // ---- Early out only if EVERY row in the group is empty ----
    int any = 0;
    #pragma unroll
    for (int j = 0; j < RPW; j++) any |= hd[j];
    if (any == 0) return;            // heads already 0; no reset needed

    int posb[RPW];
    #pragma unroll
    for (int j = 0; j < RPW; j++) posb[j] = -1;

    // ---- First entries: batched, full ILP, single interleaved reduction ----
    int e[RPW], nxt[RPW];
    float s[RPW];
    #pragma unroll
    for (int j = 0; j < RPW; j++) {
        e[j] = hd[j];
        nxt[j] = (e[j] > 0) ? g_next[e[j] - 1] : 0;
    }
    #pragma unroll
    for (int j = 0; j < RPW; j++) {
        if (e[j] > 0) {
            unsigned int b = (unsigned int)(e[j] - 1) / (unsigned int)Kp1;
            float4 xv = x4[b * 32 + lane];               // L1/L2-resident
            s[j] = v[j].x * xv.x + v[j].y * xv.y
                 + v[j].z * xv.z + v[j].w * xv.w;
        } else {
            s[j] = 0.0f;
        }
    }
    #pragma unroll
    for (int o = 16; o > 0; o >>= 1) {
        #pragma unroll
        for (int j = 0; j < RPW; j++) {
            s[j] += __shfl_xor_sync(0xffffffffu, s[j], o);
        }
    }
    #pragma unroll
    for (int j = 0; j < RPW; j++) {
        if (e[j] > 0) {
            int eid = e[j] - 1;
            unsigned int b = (unsigned int)eid / (unsigned int)Kp1;
            int k = eid - (int)b * Kp1;
            if (lane == 0) out[eid] = s[j] * invT;
            if (k == 0) posb[j] = max(posb[j], (int)b);
        }
    }

    // ---- Continuation for chains of length >= 2 (rare) ----
    #pragma unroll
    for (int j = 0; j < RPW; j++) {
        int ee = nxt[j];
        while (ee > 0) {
            int eid = ee - 1;
            unsigned int b = (unsigned int)eid / (unsigned int)Kp1;
            int k = eid - (int)b * Kp1;
            float4 xv = x4[b * 32 + lane];
            float ss = v[j].x * xv.x + v[j].y * xv.y
                     + v[j].z * xv.z + v[j].w * xv.w;
            #pragma unroll
            for (int o = 16; o > 0; o >>= 1)
                ss += __shfl_xor_sync(0xffffffffu, ss, o);
            if (lane == 0) out[eid] = ss * invT;
            if (k == 0) posb[j] = max(posb[j], (int)b);
            ee = g_next[eid];
        }
    }

    // ---- Momentum update overwrite (~256 rows grid-wide) ----
    #pragma unroll
    for (int j = 0; j < RPW; j++) {
        if (posb[j] >= 0) {
            float4 xv = x4[posb[j] * 32 + lane];
            float4 w;
            w.x = 0.5f * v[j].x + 0.5f * xv.x;
            w.y = 0.5f * v[j].y + 0.5f * xv.y;
            w.z = 0.5f * v[j].z + 0.5f * xv.z;
            w.w = 0.5f * v[j].w + 0.5f * xv.w;
            float ss = w.x * w.x + w.y * w.y + w.z * w.z + w.w * w.w;
            #pragma unroll
            for (int o = 16; o > 0; o >>= 1)
                ss += __shfl_xor_sync(0xffffffffu, ss, o);
            float inv = 1.0f / sqrtf(ss);
            w.x *= inv; w.y *= inv; w.z *= inv; w.w *= inv;
            dst[j * 32] = w;
        }
    }

    // ---- Reset this warp's heads for the next launch / graph replay ----
    if (lane < RPW) {
        if (EXACT || r0 + lane < N) g_head[r0 + lane] = 0;
    }
}

// ----------------------------------------------------------------------------
// Launch. Inputs: x [B,D] f32, memory [N,D] f32, y [B] i32, idx [B,K+1] i32.
// Output: out [B,K+1] f32 then new_memory [N,D] f32.
// ----------------------------------------------------------------------------
extern "C" void kernel_launch(void* const* d_in, const int* in_sizes, int n_in,
                              void* d_out, int out_size) {
    const float* x      = (const float*)d_in[0];
    const float* memory = (const float*)d_in[1];
    const int*   idx    = (const int*)d_in[3];

    int B   = in_sizes[2];                  // 256
    int D   = in_sizes[0] / B;              // 128
    int Kp1 = in_sizes[3] / B;              // 4097
    int N   = in_sizes[1] / D;              // 1,000,000

    float* out_scores = (float*)d_out;
    float* new_memory = (float*)d_out + (long long)in_sizes[3];

    const float invT = 1.0f / 0.07f;

    // B) bin score entries by memory row (heads are clean: zero at load,
    //    reset by the previous fused-kernel epilogue on later replays)
    {
        dim3 grid((Kp1 + 255) / 256, B);
        bin_kernel<<<grid, 256>>>(idx, Kp1);
    }

    // C) fused copy + scores + positive update
    {
        int threads = 256;                           // 8 warps/block
        int rows_per_block = (threads / 32) * RPW;   // 64
        int blocks = (N + rows_per_block - 1) / rows_per_block;
        bool exact = (N % rows_per_block) == 0;      // 1e6 / 64 = 15625 exact
        if (Kp1 == 4097 && exact) {
            fused_copy_score_kernel<4097, true><<<blocks, threads>>>(
                (const float4*)memory, (float4*)new_memory,
                (const float4*)x, out_scores, N, Kp1, invT);
        } else if (exact) {
            fused_copy_score_kernel<0, true><<<blocks, threads>>>(
                (const float4*)memory, (float4*)new_memory,
                (const float4*)x, out_scores, N, Kp1, invT);
        } else {
            fused_copy_score_kernel<0, false><<<blocks, threads>>>(
                (const float4*)memory, (float4*)new_memory,
                (const float4*)x, out_scores, N, Kp1, invT);
        }
    }
}